// round 9
// baseline (speedup 1.0000x reference)
#include <cuda_runtime.h>
#include <cuda_bf16.h>
#include <math.h>
#include <stdint.h>

// Problem constants
#define TT 512
#define NN 32
#define CC 1296
#define DD 512
#define SS 30
#define LL 61
#define MM (TT*NN)              // 16384
#define NORM_SCALE 32.0f
#define NEGINF (-1e9f)
#define NCB 11                  // n-blocks of 128
#define CPAD (NCB * 128)        // 1408

// ---------------- scratch ----------------
__device__ __nv_bfloat16 g_fb[(size_t)MM * DD];     // feats bf16 [m][d]
__device__ __nv_bfloat16 g_wb[(size_t)CPAD * DD];   // normalized weight transposed [c][d]
__device__ float g_scale[MM];
__device__ float g_psum[(size_t)NCB * MM];          // per-cblock sum of exp(logit-32)
__device__ float g_lpraw[32 * MM];                  // slot-indexed raw logits [slot][m]
__device__ unsigned char g_slot[NN * CPAD];         // class -> slot+1 (0 = unused)
__device__ float g_nll[NN];

// ---------------- helpers ----------------
__device__ __forceinline__ uint32_t smem_u32(const void* p) {
    uint32_t a;
    asm("{ .reg .u64 t; cvta.to.shared.u64 t, %1; cvt.u32.u64 %0, t; }" : "=r"(a) : "l"(p));
    return a;
}
__device__ __forceinline__ void cp_async16(uint32_t sa, const void* ga) {
    asm volatile("cp.async.cg.shared.global [%0], [%1], 16;" :: "r"(sa), "l"(ga) : "memory");
}
#define CP_COMMIT() asm volatile("cp.async.commit_group;" ::: "memory")
#define CP_WAIT(n)  asm volatile("cp.async.wait_group %0;" :: "n"(n) : "memory")

__device__ __forceinline__ void ldsm4(uint32_t& r0, uint32_t& r1, uint32_t& r2, uint32_t& r3,
                                      uint32_t addr) {
    asm volatile("ldmatrix.sync.aligned.m8n8.x4.shared.b16 {%0,%1,%2,%3}, [%4];"
                 : "=r"(r0), "=r"(r1), "=r"(r2), "=r"(r3) : "r"(addr));
}
__device__ __forceinline__ void mma16816(float* d, const uint32_t* a, uint32_t b0, uint32_t b1) {
    asm volatile("mma.sync.aligned.m16n8k16.row.col.f32.bf16.bf16.f32 "
                 "{%0,%1,%2,%3}, {%4,%5,%6,%7}, {%8,%9}, {%0,%1,%2,%3};"
                 : "+f"(d[0]), "+f"(d[1]), "+f"(d[2]), "+f"(d[3])
                 : "r"(a[0]), "r"(a[1]), "r"(a[2]), "r"(a[3]), "r"(b0), "r"(b1));
}

// ---------------- 1. normalize weight columns -> transposed bf16 [c][d] ----------------
__global__ void wnorm_kernel(const float* __restrict__ w) {
    int c = blockIdx.x * blockDim.x + threadIdx.x;
    if (c >= CPAD) return;
    if (c >= CC) {
        for (int d = 0; d < DD; d++) g_wb[(size_t)c * DD + d] = __float2bfloat16(0.f);
        return;
    }
    float ss = 0.f;
    #pragma unroll 8
    for (int d = 0; d < DD; d++) { float v = w[d * CC + c]; ss += v * v; }
    float inv = rsqrtf(ss);
    #pragma unroll 8
    for (int d = 0; d < DD; d++)
        g_wb[(size_t)c * DD + d] = __float2bfloat16(w[d * CC + c] * inv);
}

// ---------------- 1b. class -> slot table ----------------
__global__ void slot_kernel(const int* __restrict__ labeling) {
    const int tid = threadIdx.x;
    int* sl = (int*)g_slot;
    for (int i = tid; i < NN * CPAD / 4; i += 1024) sl[i] = 0;
    __syncthreads();
    if (tid < NN) {
        g_slot[tid * CPAD + 0] = 1;                 // blank -> slot 1 (index 0)
        for (int i = 0; i < SS; i++) {
            int cls = labeling[tid * SS + i];
            g_slot[tid * CPAD + cls] = (unsigned char)(i + 2);
        }
    }
}

// ---------------- 2. per-row scale + bf16 convert ----------------
__global__ void fscale_kernel(const float* __restrict__ f) {
    int row = blockIdx.x * (blockDim.x >> 5) + (threadIdx.x >> 5);
    int lane = threadIdx.x & 31;
    if (row >= MM) return;
    const float4* fr = (const float4*)(f + (size_t)row * DD);
    __nv_bfloat16* ob = g_fb + (size_t)row * DD;
    float ss = 0.f;
    #pragma unroll
    for (int i = lane; i < DD / 4; i += 32) {
        float4 v = fr[i];
        ss += v.x * v.x + v.y * v.y + v.z * v.z + v.w * v.w;
        ob[i * 4 + 0] = __float2bfloat16(v.x);
        ob[i * 4 + 1] = __float2bfloat16(v.y);
        ob[i * 4 + 2] = __float2bfloat16(v.z);
        ob[i * 4 + 3] = __float2bfloat16(v.w);
    }
    #pragma unroll
    for (int o = 16; o; o >>= 1) ss += __shfl_xor_sync(0xffffffffu, ss, o);
    if (lane == 0) g_scale[row] = NORM_SCALE * rsqrtf(ss);
}

// ---------------- 3. bf16 mma.sync GEMM + fused exp/gather epilogue ----------------
// Block tile 128m x 128n, BK=64, 3-stage cp.async pipeline, 256 thr = 8 warps (4m x 2n).
#define GBK 64
#define KCH (DD / GBK)          // 8
#define TILE_B 16384            // one operand tile: 128 rows * 128B
#define BUF_B (2 * TILE_B)      // A + B per stage
#define GEMM_SMEM (3 * BUF_B + 1024)

__global__ void __launch_bounds__(256, 2) gemm_kernel() {
    extern __shared__ char smraw[];
    const uint32_t base = (smem_u32(smraw) + 1023u) & ~1023u;
    const int tid = threadIdx.x;
    const int wid = tid >> 5;
    const int lane = tid & 31;
    const int bm = blockIdx.y * 128;
    const int bn = blockIdx.x * 128;
    const int wm = (wid >> 1) * 32;
    const int wn = (wid & 1) * 64;

    auto load_tile = [&](uint32_t sbuf, const __nv_bfloat16* gsrc, int kt) {
        const char* g = (const char*)gsrc + (size_t)kt * 128;
        #pragma unroll
        for (int r = 0; r < 4; r++) {
            int s = tid + r * 256;
            int row = s >> 3, kc = s & 7;
            cp_async16(sbuf + (uint32_t)(row * 128 + ((kc ^ (row & 7)) * 16)),
                       g + (size_t)row * 1024 + kc * 16);
        }
    };
    auto load_chunk = [&](int kt) {
        uint32_t off = (uint32_t)(kt % 3) * BUF_B;
        load_tile(base + off, g_fb + (size_t)bm * DD, kt);
        load_tile(base + off + TILE_B, g_wb + (size_t)bn * DD, kt);
        CP_COMMIT();
    };

    float acc[2][8][4];
    #pragma unroll
    for (int i = 0; i < 2; i++)
        #pragma unroll
        for (int j = 0; j < 8; j++)
            #pragma unroll
            for (int r = 0; r < 4; r++) acc[i][j][r] = 0.f;

    const int a_row_l = lane & 15;
    const int a_coff = lane >> 4;
    const int b_row_l = ((lane >> 4) << 3) + (lane & 7);
    const int b_coff = (lane >> 3) & 1;

    load_chunk(0);
    load_chunk(1);
    #pragma unroll 1
    for (int kt = 0; kt < KCH; kt++) {
        if (kt + 1 < KCH) CP_WAIT(1); else CP_WAIT(0);
        __syncthreads();
        if (kt + 2 < KCH) load_chunk(kt + 2);
        const uint32_t Ab = base + (uint32_t)(kt % 3) * BUF_B;
        const uint32_t Bb = Ab + TILE_B;
        #pragma unroll
        for (int ks = 0; ks < 4; ks++) {
            uint32_t a[2][4], b[4][4];
            #pragma unroll
            for (int mt = 0; mt < 2; mt++) {
                int row = wm + mt * 16 + a_row_l;
                int kc = ks * 2 + a_coff;
                ldsm4(a[mt][0], a[mt][1], a[mt][2], a[mt][3],
                      Ab + (uint32_t)(row * 128 + ((kc ^ (row & 7)) * 16)));
            }
            #pragma unroll
            for (int p = 0; p < 4; p++) {
                int row = wn + p * 16 + b_row_l;
                int kc = ks * 2 + b_coff;
                ldsm4(b[p][0], b[p][1], b[p][2], b[p][3],
                      Bb + (uint32_t)(row * 128 + ((kc ^ (row & 7)) * 16)));
            }
            #pragma unroll
            for (int mt = 0; mt < 2; mt++)
                #pragma unroll
                for (int p = 0; p < 4; p++) {
                    mma16816(acc[mt][2 * p + 0], a[mt], b[p][0], b[p][1]);
                    mma16816(acc[mt][2 * p + 1], a[mt], b[p][2], b[p][3]);
                }
        }
    }
    __syncthreads();                                // buffers dead; smraw reused below

    // epilogue: scale, slot-gather writes, fused per-row sum of exp(logit-32)
    float* ps = (float*)smraw;                      // [128 rows][2 n-warps]
    #pragma unroll
    for (int mt = 0; mt < 2; mt++) {
        const int lr0 = wm + mt * 16 + (lane >> 2);
        const int lr1 = lr0 + 8;
        const int row0 = bm + lr0, row1 = bm + lr1;
        const float s0 = g_scale[row0];
        const float s1 = g_scale[row1];
        const unsigned char* sl0 = g_slot + (size_t)(row0 & 31) * CPAD;
        const unsigned char* sl1 = g_slot + (size_t)(row1 & 31) * CPAD;
        float e0 = 0.f, e1 = 0.f;
        #pragma unroll
        for (int j = 0; j < 8; j++) {
            int c0 = bn + wn + (j >> 1) * 16 + (j & 1) * 8 + (lane & 3) * 2;
            float v00 = s0 * acc[mt][j][0], v01 = s0 * acc[mt][j][1];
            float v10 = s1 * acc[mt][j][2], v11 = s1 * acc[mt][j][3];
            if (c0 < CC) {
                e0 += __expf(v00 - 32.f);
                e1 += __expf(v10 - 32.f);
                unsigned char t0 = sl0[c0], t1 = sl1[c0];
                if (t0) g_lpraw[(size_t)(t0 - 1) * MM + row0] = v00;
                if (t1) g_lpraw[(size_t)(t1 - 1) * MM + row1] = v10;
            }
            if (c0 + 1 < CC) {
                e0 += __expf(v01 - 32.f);
                e1 += __expf(v11 - 32.f);
                unsigned char t0 = sl0[c0 + 1], t1 = sl1[c0 + 1];
                if (t0) g_lpraw[(size_t)(t0 - 1) * MM + row0] = v01;
                if (t1) g_lpraw[(size_t)(t1 - 1) * MM + row1] = v11;
            }
        }
        e0 += __shfl_xor_sync(0xffffffffu, e0, 1);
        e0 += __shfl_xor_sync(0xffffffffu, e0, 2);
        e1 += __shfl_xor_sync(0xffffffffu, e1, 1);
        e1 += __shfl_xor_sync(0xffffffffu, e1, 2);
        if ((lane & 3) == 0) {
            ps[lr0 * 2 + (wid & 1)] = e0;
            ps[lr1 * 2 + (wid & 1)] = e1;
        }
    }
    __syncthreads();
    if (tid < 128)
        g_psum[(size_t)blockIdx.x * MM + bm + tid] = ps[tid * 2] + ps[tid * 2 + 1];
}

// ---------------- 4. CTC: fused lse-combine + gather + warp recursion ----------------
#define CTC_SMEM (TT * 32 * 4 + TT * 4 + 32 * 4)
__global__ void __launch_bounds__(128) ctc_kernel(const int* __restrict__ labeling,
                                                  const int* __restrict__ in_lens,
                                                  const int* __restrict__ lab_lens) {
    extern __shared__ float sm[];
    float* slp = sm;                       // [512][32]
    float* slse = sm + TT * 32;            // [512]
    int* ssrc = (int*)(slse + TT);         // [32] slot index per lp row
    const int n = blockIdx.x;
    const int tid = threadIdx.x;

    if (tid < 32) {
        int src = 0;
        if (tid >= 1) {
            int cls = labeling[n * SS + tid - 1];
            src = (int)g_slot[(size_t)n * CPAD + cls] - 1;
        }
        ssrc[tid] = src;
    }
    for (int t = tid; t < TT; t += 128) {
        float ssum = 0.f;
        #pragma unroll
        for (int cb = 0; cb < NCB; cb++) ssum += g_psum[(size_t)cb * MM + (t << 5) + n];
        slse[t] = 32.f + __logf(ssum);
    }
    __syncthreads();
    for (int idx = tid; idx < TT * 32; idx += 128) {
        int t = idx >> 5, i = idx & 31;
        slp[idx] = g_lpraw[(size_t)ssrc[i] * MM + (t << 5) + n] - slse[t];
    }
    __syncthreads();
    if (tid >= 32) return;
    const int l = tid;
    bool skip = false;
    if (l >= 1 && l < SS)
        skip = labeling[n * SS + l] != labeling[n * SS + l - 1];
    const bool odd_valid = (l < 30);
    float e = (l == 0) ? slp[0] : NEGINF;
    float o = (l == 0) ? slp[1] : NEGINF;
    const int Tn = in_lens[n];
    for (int t = 1; t < Tn; t++) {
        float po = __shfl_up_sync(0xffffffffu, o, 1);
        if (l == 0) po = NEGINF;
        float lpb = slp[t << 5];
        float lpo = odd_valid ? slp[(t << 5) + 1 + l] : NEGINF;
        float m1 = fmaxf(e, po);
        float ne = m1 + __logf(__expf(e - m1) + __expf(po - m1)) + lpb;
        float a3 = skip ? po : NEGINF;
        float m2 = fmaxf(o, fmaxf(e, a3));
        float no = m2 + __logf(__expf(o - m2) + __expf(e - m2) + __expf(a3 - m2)) + lpo;
        e = ne; o = no;
    }
    const int labn = lab_lens[n];
    float x = __shfl_sync(0xffffffffu, e, labn);
    float y = __shfl_sync(0xffffffffu, o, labn - 1);
    if (l == 0) {
        float m = fmaxf(x, y);
        g_nll[n] = -(m + __logf(__expf(x - m) + __expf(y - m)));
    }
}

// ---------------- 5. deterministic sum ----------------
__global__ void sum_kernel(float* __restrict__ out) {
    if (threadIdx.x == 0) {
        float t = 0.f;
        #pragma unroll
        for (int i = 0; i < NN; i++) t += g_nll[i];
        out[0] = t;
    }
}

// ---------------- launch ----------------
extern "C" void kernel_launch(void* const* d_in, const int* in_sizes, int n_in,
                              void* d_out, int out_size) {
    const float* feats = (const float*)d_in[0];
    const float* weight = (const float*)d_in[1];
    const int* labeling = (const int*)d_in[2];
    const int* logit_lgts = (const int*)d_in[3];
    const int* labeling_lgts = (const int*)d_in[4];
    float* out = (float*)d_out;

    cudaFuncSetAttribute(gemm_kernel, cudaFuncAttributeMaxDynamicSharedMemorySize, GEMM_SMEM);
    cudaFuncSetAttribute(ctc_kernel, cudaFuncAttributeMaxDynamicSharedMemorySize, CTC_SMEM);

    wnorm_kernel<<<CPAD / 128, 128>>>(weight);
    slot_kernel<<<1, 1024>>>(labeling);
    fscale_kernel<<<MM / 8, 256>>>(feats);
    gemm_kernel<<<dim3(NCB, MM / 128), 256, GEMM_SMEM>>>();   // 11 x 128 blocks
    ctc_kernel<<<NN, 128, CTC_SMEM>>>(labeling, logit_lgts, labeling_lgts);
    sum_kernel<<<1, 32>>>(out);
}

// round 10
// speedup vs baseline: 1.4893x; 1.4893x over previous
#include <cuda_runtime.h>
#include <cuda_bf16.h>
#include <math.h>
#include <stdint.h>

// Problem constants
#define TT 512
#define NN 32
#define CC 1296
#define DD 512
#define SS 30
#define LL 61
#define MM (TT*NN)              // 16384
#define NORM_SCALE 32.0f
#define NEGINF (-1e9f)
#define NCB 11                  // n-blocks of 128
#define CPAD (NCB * 128)        // 1408

// ---------------- scratch ----------------
__device__ __nv_bfloat16 g_fb[(size_t)MM * DD];     // feats bf16 [m][d]
__device__ __nv_bfloat16 g_wb[(size_t)CPAD * DD];   // normalized weight transposed [c][d]
__device__ float g_scale[MM];
__device__ float g_psumT[(size_t)MM * 16];          // per-row, per-cblock sum exp(logit-32)
__device__ float g_lpraw[(size_t)MM * 32];          // [m][slot] raw logits
__device__ unsigned char g_slot[NN * CPAD];         // class -> slot+1 (0 = unused)
__device__ int g_src[NN * 32];                      // lp row i -> slot index
__device__ float g_nll[NN];

// ---------------- helpers ----------------
__device__ __forceinline__ uint32_t smem_u32(const void* p) {
    uint32_t a;
    asm("{ .reg .u64 t; cvta.to.shared.u64 t, %1; cvt.u32.u64 %0, t; }" : "=r"(a) : "l"(p));
    return a;
}
__device__ __forceinline__ void cp_async16(uint32_t sa, const void* ga) {
    asm volatile("cp.async.cg.shared.global [%0], [%1], 16;" :: "r"(sa), "l"(ga) : "memory");
}
#define CP_COMMIT() asm volatile("cp.async.commit_group;" ::: "memory")
#define CP_WAIT(n)  asm volatile("cp.async.wait_group %0;" :: "n"(n) : "memory")

__device__ __forceinline__ void ldsm4(uint32_t& r0, uint32_t& r1, uint32_t& r2, uint32_t& r3,
                                      uint32_t addr) {
    asm volatile("ldmatrix.sync.aligned.m8n8.x4.shared.b16 {%0,%1,%2,%3}, [%4];"
                 : "=r"(r0), "=r"(r1), "=r"(r2), "=r"(r3) : "r"(addr));
}
__device__ __forceinline__ void mma16816(float* d, const uint32_t* a, uint32_t b0, uint32_t b1) {
    asm volatile("mma.sync.aligned.m16n8k16.row.col.f32.bf16.bf16.f32 "
                 "{%0,%1,%2,%3}, {%4,%5,%6,%7}, {%8,%9}, {%0,%1,%2,%3};"
                 : "+f"(d[0]), "+f"(d[1]), "+f"(d[2]), "+f"(d[3])
                 : "r"(a[0]), "r"(a[1]), "r"(a[2]), "r"(a[3]), "r"(b0), "r"(b1));
}

// ---------------- 1. normalize weight: one warp per column ----------------
__global__ void __launch_bounds__(256) wnorm_kernel(const float* __restrict__ w) {
    const int c = (blockIdx.x * 256 + threadIdx.x) >> 5;
    const int lane = threadIdx.x & 31;
    if (c >= CPAD) return;
    if (c >= CC) {
        #pragma unroll
        for (int i = 0; i < 16; i++)
            g_wb[(size_t)c * DD + i * 32 + lane] = __float2bfloat16(0.f);
        return;
    }
    float vals[16];
    float ss = 0.f;
    #pragma unroll
    for (int i = 0; i < 16; i++) {
        float v = w[(size_t)(i * 32 + lane) * CC + c];
        vals[i] = v;
        ss += v * v;
    }
    #pragma unroll
    for (int o = 16; o; o >>= 1) ss += __shfl_xor_sync(0xffffffffu, ss, o);
    const float inv = rsqrtf(ss);
    #pragma unroll
    for (int i = 0; i < 16; i++)
        g_wb[(size_t)c * DD + i * 32 + lane] = __float2bfloat16(vals[i] * inv);
}

// ---------------- 1b. class->slot table + lp-row source table ----------------
__global__ void slot_kernel(const int* __restrict__ labeling) {
    const int tid = threadIdx.x;
    int* sl = (int*)g_slot;
    for (int i = tid; i < NN * CPAD / 4; i += 1024) sl[i] = 0;
    __syncthreads();
    if (tid < NN) {
        g_slot[tid * CPAD + 0] = 1;                 // blank -> slot 1 (index 0)
        for (int i = 0; i < SS; i++) {
            int cls = labeling[tid * SS + i];
            g_slot[tid * CPAD + cls] = (unsigned char)(i + 2);
        }
    }
    __syncthreads();
    if (tid < NN) {
        g_src[tid * 32 + 0] = 0;
        for (int i = 1; i <= SS; i++) {
            int cls = labeling[tid * SS + i - 1];
            g_src[tid * 32 + i] = (int)g_slot[tid * CPAD + cls] - 1;
        }
        g_src[tid * 32 + 31] = 0;                   // unused
    }
}

// ---------------- 2. per-row scale + bf16 convert ----------------
__global__ void fscale_kernel(const float* __restrict__ f) {
    int row = blockIdx.x * (blockDim.x >> 5) + (threadIdx.x >> 5);
    int lane = threadIdx.x & 31;
    if (row >= MM) return;
    const float4* fr = (const float4*)(f + (size_t)row * DD);
    __nv_bfloat16* ob = g_fb + (size_t)row * DD;
    float ss = 0.f;
    #pragma unroll
    for (int i = lane; i < DD / 4; i += 32) {
        float4 v = fr[i];
        ss += v.x * v.x + v.y * v.y + v.z * v.z + v.w * v.w;
        ob[i * 4 + 0] = __float2bfloat16(v.x);
        ob[i * 4 + 1] = __float2bfloat16(v.y);
        ob[i * 4 + 2] = __float2bfloat16(v.z);
        ob[i * 4 + 3] = __float2bfloat16(v.w);
    }
    #pragma unroll
    for (int o = 16; o; o >>= 1) ss += __shfl_xor_sync(0xffffffffu, ss, o);
    if (lane == 0) g_scale[row] = NORM_SCALE * rsqrtf(ss);
}

// ---------------- 3. bf16 mma.sync GEMM + fused exp/gather epilogue ----------------
// Block tile 128m x 128n, BK=64, 3-stage cp.async pipeline, 256 thr = 8 warps (4m x 2n).
#define GBK 64
#define KCH (DD / GBK)          // 8
#define TILE_B 16384
#define BUF_B (2 * TILE_B)
#define GEMM_SMEM (3 * BUF_B + 1024)

__global__ void __launch_bounds__(256, 2) gemm_kernel() {
    extern __shared__ char smraw[];
    const uint32_t base = (smem_u32(smraw) + 1023u) & ~1023u;
    const int tid = threadIdx.x;
    const int wid = tid >> 5;
    const int lane = tid & 31;
    const int bm = blockIdx.y * 128;
    const int bn = blockIdx.x * 128;
    const int wm = (wid >> 1) * 32;
    const int wn = (wid & 1) * 64;

    auto load_tile = [&](uint32_t sbuf, const __nv_bfloat16* gsrc, int kt) {
        const char* g = (const char*)gsrc + (size_t)kt * 128;
        #pragma unroll
        for (int r = 0; r < 4; r++) {
            int s = tid + r * 256;
            int row = s >> 3, kc = s & 7;
            cp_async16(sbuf + (uint32_t)(row * 128 + ((kc ^ (row & 7)) * 16)),
                       g + (size_t)row * 1024 + kc * 16);
        }
    };
    auto load_chunk = [&](int kt) {
        uint32_t off = (uint32_t)(kt % 3) * BUF_B;
        load_tile(base + off, g_fb + (size_t)bm * DD, kt);
        load_tile(base + off + TILE_B, g_wb + (size_t)bn * DD, kt);
        CP_COMMIT();
    };

    float acc[2][8][4];
    #pragma unroll
    for (int i = 0; i < 2; i++)
        #pragma unroll
        for (int j = 0; j < 8; j++)
            #pragma unroll
            for (int r = 0; r < 4; r++) acc[i][j][r] = 0.f;

    const int a_row_l = lane & 15;
    const int a_coff = lane >> 4;
    const int b_row_l = ((lane >> 4) << 3) + (lane & 7);
    const int b_coff = (lane >> 3) & 1;

    load_chunk(0);
    load_chunk(1);
    #pragma unroll 1
    for (int kt = 0; kt < KCH; kt++) {
        if (kt + 1 < KCH) CP_WAIT(1); else CP_WAIT(0);
        __syncthreads();
        if (kt + 2 < KCH) load_chunk(kt + 2);
        const uint32_t Ab = base + (uint32_t)(kt % 3) * BUF_B;
        const uint32_t Bb = Ab + TILE_B;
        #pragma unroll
        for (int ks = 0; ks < 4; ks++) {
            uint32_t a[2][4], b[4][4];
            #pragma unroll
            for (int mt = 0; mt < 2; mt++) {
                int row = wm + mt * 16 + a_row_l;
                int kc = ks * 2 + a_coff;
                ldsm4(a[mt][0], a[mt][1], a[mt][2], a[mt][3],
                      Ab + (uint32_t)(row * 128 + ((kc ^ (row & 7)) * 16)));
            }
            #pragma unroll
            for (int p = 0; p < 4; p++) {
                int row = wn + p * 16 + b_row_l;
                int kc = ks * 2 + b_coff;
                ldsm4(b[p][0], b[p][1], b[p][2], b[p][3],
                      Bb + (uint32_t)(row * 128 + ((kc ^ (row & 7)) * 16)));
            }
            #pragma unroll
            for (int mt = 0; mt < 2; mt++)
                #pragma unroll
                for (int p = 0; p < 4; p++) {
                    mma16816(acc[mt][2 * p + 0], a[mt], b[p][0], b[p][1]);
                    mma16816(acc[mt][2 * p + 1], a[mt], b[p][2], b[p][3]);
                }
        }
    }
    __syncthreads();                                // buffers dead; smraw reused below

    // epilogue: scale, slot-gather writes ([m][32] layout), per-row exp partial
    float* ps = (float*)smraw;                      // [128 rows][2 n-warps]
    #pragma unroll
    for (int mt = 0; mt < 2; mt++) {
        const int lr0 = wm + mt * 16 + (lane >> 2);
        const int lr1 = lr0 + 8;
        const int row0 = bm + lr0, row1 = bm + lr1;
        const float s0 = g_scale[row0];
        const float s1 = g_scale[row1];
        const unsigned char* sl0 = g_slot + (size_t)(row0 & 31) * CPAD;
        const unsigned char* sl1 = g_slot + (size_t)(row1 & 31) * CPAD;
        float e0 = 0.f, e1 = 0.f;
        #pragma unroll
        for (int j = 0; j < 8; j++) {
            int c0 = bn + wn + (j >> 1) * 16 + (j & 1) * 8 + (lane & 3) * 2;
            float v00 = s0 * acc[mt][j][0], v01 = s0 * acc[mt][j][1];
            float v10 = s1 * acc[mt][j][2], v11 = s1 * acc[mt][j][3];
            if (c0 < CC) {
                e0 += __expf(v00 - 32.f);
                e1 += __expf(v10 - 32.f);
                unsigned char t0 = sl0[c0], t1 = sl1[c0];
                if (t0) g_lpraw[(size_t)row0 * 32 + t0 - 1] = v00;
                if (t1) g_lpraw[(size_t)row1 * 32 + t1 - 1] = v10;
            }
            if (c0 + 1 < CC) {
                e0 += __expf(v01 - 32.f);
                e1 += __expf(v11 - 32.f);
                unsigned char t0 = sl0[c0 + 1], t1 = sl1[c0 + 1];
                if (t0) g_lpraw[(size_t)row0 * 32 + t0 - 1] = v01;
                if (t1) g_lpraw[(size_t)row1 * 32 + t1 - 1] = v11;
            }
        }
        e0 += __shfl_xor_sync(0xffffffffu, e0, 1);
        e0 += __shfl_xor_sync(0xffffffffu, e0, 2);
        e1 += __shfl_xor_sync(0xffffffffu, e1, 1);
        e1 += __shfl_xor_sync(0xffffffffu, e1, 2);
        if ((lane & 3) == 0) {
            ps[lr0 * 2 + (wid & 1)] = e0;
            ps[lr1 * 2 + (wid & 1)] = e1;
        }
    }
    __syncthreads();
    if (tid < 128)
        g_psumT[(size_t)(bm + tid) * 16 + blockIdx.x] = ps[tid * 2] + ps[tid * 2 + 1];
}

// ---------------- 4. CTC: coalesced lse+gather staging + warp recursion ----------------
#define CTC_SMEM (TT * 32 * 4 + TT * 4 + 32 * 4)
__global__ void __launch_bounds__(128) ctc_kernel(const int* __restrict__ labeling,
                                                  const int* __restrict__ in_lens,
                                                  const int* __restrict__ lab_lens) {
    extern __shared__ float sm[];
    float* slp = sm;                       // [512][32]
    float* slse = sm + TT * 32;            // [512]
    int* ssrc = (int*)(slse + TT);         // [32]
    const int n = blockIdx.x;
    const int tid = threadIdx.x;

    if (tid < 32) ssrc[tid] = g_src[n * 32 + tid];
    // lse per t: dense 44B read per thread from psumT
    for (int t = tid; t < TT; t += 128) {
        const float* pp = g_psumT + (size_t)((t << 5) + n) * 16;
        float ssum = 0.f;
        #pragma unroll
        for (int cb = 0; cb < NCB; cb++) ssum += pp[cb];
        slse[t] = 32.f + __logf(ssum);
    }
    __syncthreads();
    // gather: warp reads one 128B line of lpraw per iteration (permuted in-line)
    for (int idx = tid; idx < TT * 32; idx += 128) {
        int t = idx >> 5, i = idx & 31;
        slp[idx] = g_lpraw[(size_t)((t << 5) + n) * 32 + ssrc[i]] - slse[t];
    }
    __syncthreads();
    if (tid >= 32) return;
    const int l = tid;
    bool skip = false;
    if (l >= 1 && l < SS)
        skip = labeling[n * SS + l] != labeling[n * SS + l - 1];
    const bool odd_valid = (l < 30);
    float e = (l == 0) ? slp[0] : NEGINF;
    float o = (l == 0) ? slp[1] : NEGINF;
    const int Tn = in_lens[n];
    for (int t = 1; t < Tn; t++) {
        float po = __shfl_up_sync(0xffffffffu, o, 1);
        if (l == 0) po = NEGINF;
        float lpb = slp[t << 5];
        float lpo = odd_valid ? slp[(t << 5) + 1 + l] : NEGINF;
        float m1 = fmaxf(e, po);
        float ne = m1 + __logf(__expf(e - m1) + __expf(po - m1)) + lpb;
        float a3 = skip ? po : NEGINF;
        float m2 = fmaxf(o, fmaxf(e, a3));
        float no = m2 + __logf(__expf(o - m2) + __expf(e - m2) + __expf(a3 - m2)) + lpo;
        e = ne; o = no;
    }
    const int labn = lab_lens[n];
    float x = __shfl_sync(0xffffffffu, e, labn);
    float y = __shfl_sync(0xffffffffu, o, labn - 1);
    if (l == 0) {
        float m = fmaxf(x, y);
        g_nll[n] = -(m + __logf(__expf(x - m) + __expf(y - m)));
    }
}

// ---------------- 5. deterministic sum ----------------
__global__ void sum_kernel(float* __restrict__ out) {
    if (threadIdx.x == 0) {
        float t = 0.f;
        #pragma unroll
        for (int i = 0; i < NN; i++) t += g_nll[i];
        out[0] = t;
    }
}

// ---------------- launch ----------------
extern "C" void kernel_launch(void* const* d_in, const int* in_sizes, int n_in,
                              void* d_out, int out_size) {
    const float* feats = (const float*)d_in[0];
    const float* weight = (const float*)d_in[1];
    const int* labeling = (const int*)d_in[2];
    const int* logit_lgts = (const int*)d_in[3];
    const int* labeling_lgts = (const int*)d_in[4];
    float* out = (float*)d_out;

    cudaFuncSetAttribute(gemm_kernel, cudaFuncAttributeMaxDynamicSharedMemorySize, GEMM_SMEM);
    cudaFuncSetAttribute(ctc_kernel, cudaFuncAttributeMaxDynamicSharedMemorySize, CTC_SMEM);

    wnorm_kernel<<<(CPAD * 32 + 255) / 256, 256>>>(weight);   // one warp per column
    slot_kernel<<<1, 1024>>>(labeling);
    fscale_kernel<<<MM / 8, 256>>>(feats);
    gemm_kernel<<<dim3(NCB, MM / 128), 256, GEMM_SMEM>>>();
    ctc_kernel<<<NN, 128, CTC_SMEM>>>(labeling, logit_lgts, labeling_lgts);
    sum_kernel<<<1, 32>>>(out);
}